// round 2
// baseline (speedup 1.0000x reference)
#include <cuda_runtime.h>

// DTW loss, B batches of N x M DP, fused forward DP + path-loss accumulation.
// Key identity: the reference's backtrack argmin at (i,j) over
// [D(i-1,j-1), D(i-1,j), D(i,j-1)] (first-min-wins) uses exactly the values
// available on the forward wavefront, so we carry W[i,j] = w(i,j) + W[pred]
// alongside D and the answer is W[N-1][M-1]. No backtrack, no scratch.

#define NN 1024
#define MM 1024
#define LL (NN + MM - 1)
#define RR 4            // rows per thread
#define TT 256          // threads per block (TT*RR == NN)
#define NWARP (TT / 32)

#define FINF (__int_as_float(0x7f800000))

__device__ float g_partial[64];

__global__ __launch_bounds__(TT, 1)
void dtw_forward_kernel(const float* __restrict__ preds,
                        const float* __restrict__ targs,
                        const float* __restrict__ subcoef)
{
    __shared__ float sTx[MM];
    __shared__ float sTy[MM];
    __shared__ float4 bnd[2][NWARP];   // parity-double-buffered warp boundary

    const int b    = blockIdx.x;
    const int tid  = threadIdx.x;
    const int lane = tid & 31;
    const int warp = tid >> 5;

    const float* __restrict__ pb = preds + (size_t)b * NN * 4;
    const float* __restrict__ tb = targs + (size_t)b * MM * 4;

    // stage target basis coords (features 0,1) into shared
    for (int j = tid; j < MM; j += TT) {
        sTx[j] = tb[j * 4 + 0];
        sTy[j] = tb[j * 4 + 1];
    }
    if (tid < NWARP) {
        bnd[0][tid] = make_float4(FINF, FINF, 0.f, 0.f);
        bnd[1][tid] = make_float4(FINF, FINF, 0.f, 0.f);
    }

    const float s0 = subcoef[0];
    const float s1 = subcoef[1];

    const int i0 = tid * RR;           // first row owned by this thread
    float px[RR], py[RR];
#pragma unroll
    for (int r = 0; r < RR; ++r) {
        px[r] = pb[(i0 + r) * 4 + 0];
        py[r] = pb[(i0 + r) * 4 + 1];
    }

    // per-row history: D1/W1 = diagonal k-1, D2/W2 = diagonal k-2
    float D1[RR], D2[RR], W1[RR], W2[RR];
#pragma unroll
    for (int r = 0; r < RR; ++r) { D1[r] = FINF; D2[r] = FINF; W1[r] = 0.f; W2[r] = 0.f; }

    __syncthreads();

    for (int k = 0; k < LL; ++k) {
        // neighbor-row (i0-1) history from the previous thread
        float nD1 = __shfl_up_sync(0xffffffffu, D1[RR - 1], 1);
        float nD2 = __shfl_up_sync(0xffffffffu, D2[RR - 1], 1);
        float nW1 = __shfl_up_sync(0xffffffffu, W1[RR - 1], 1);
        float nW2 = __shfl_up_sync(0xffffffffu, W2[RR - 1], 1);
        if (lane == 0) {
            if (warp == 0) {
                nD1 = FINF; nD2 = FINF; nW1 = 0.f; nW2 = 0.f;
            } else {
                float4 v = bnd[(k + 1) & 1][warp - 1];  // values after step k-1
                nD1 = v.x; nD2 = v.y; nW1 = v.z; nW2 = v.w;
            }
        }

        const int j0 = k - i0;         // column for row r is j0 - r
        if (j0 >= 0 && j0 <= MM - 1 + (RR - 1)) {
#pragma unroll
            for (int rr = RR - 1; rr >= 0; --rr) {
                float up, dg, wu, wd;
                if (rr == 0) { up = nD1; dg = nD2; wu = nW1; wd = nW2; }
                else         { up = D1[rr - 1]; dg = D2[rr - 1]; wu = W1[rr - 1]; wd = W2[rr - 1]; }
                const float lf = D1[rr];
                const float wl = W1[rr];

                const int  j     = j0 - rr;
                const bool valid = (j >= 0) && (j < MM);
                const int  jc    = j < 0 ? 0 : (j > MM - 1 ? MM - 1 : j);

                const float dx = px[rr] - sTx[jc];
                const float dy = py[rr] - sTy[jc];
                const float c  = __fsqrt_rn(dx * dx + dy * dy);
                const float w  = fabsf(dx) * s0 + fabsf(dy) * s1;

                float best = fminf(fminf(dg, up), lf);
                // first-min-wins over [diag, up, left] (matches jnp.argmin)
                float wsel = (up <= lf) ? wu : wl;
                wsel = ((dg <= up) && (dg <= lf)) ? wd : wsel;
                if (isinf(best)) { best = 0.f; wsel = 0.f; }   // (0,0) seed

                const float nD = valid ? (c + best) : FINF;
                const float nW = valid ? (w + wsel) : 0.f;
                D2[rr] = D1[rr]; D1[rr] = nD;
                W2[rr] = W1[rr]; W1[rr] = nW;
            }
        }

        if (lane == 31)
            bnd[k & 1][warp] = make_float4(D1[RR - 1], D2[RR - 1], W1[RR - 1], W2[RR - 1]);
        __syncthreads();
    }

    if (tid == TT - 1)                 // owns row N-1; W1[RR-1] = W[N-1][M-1]
        g_partial[b] = W1[RR - 1];
}

__global__ void dtw_reduce_kernel(float* __restrict__ out, int B)
{
    float s = 0.f;
    for (int i = 0; i < B; ++i) s += g_partial[i];
    out[0] = s;
}

extern "C" void kernel_launch(void* const* d_in, const int* in_sizes, int n_in,
                              void* d_out, int out_size)
{
    const float* preds   = (const float*)d_in[0];
    const float* targs   = (const float*)d_in[1];
    const float* subcoef = (const float*)d_in[2];
    float* out = (float*)d_out;

    int B = in_sizes[0] / (NN * 4);
    if (B < 1) B = 1;
    if (B > 64) B = 64;

    dtw_forward_kernel<<<B, TT>>>(preds, targs, subcoef);
    dtw_reduce_kernel<<<1, 1>>>(out, B);
}